// round 7
// baseline (speedup 1.0000x reference)
#include <cuda_runtime.h>

// Soft quantizer forward == hard nearest-level quantization (straight-through).
// levels[k] = -1 + k*(2/24), k = 0..24.
//
// HBM-streaming kernel at the DRAM roofline. Block-tiled float4 with
// __ldcg (L2-cached, L1-bypass) loads + __stcs (evict-first) streaming
// stores. TILE=16 float4 per thread (256B): maximal front-batched MLP,
// minimal per-byte issue/index overhead. Occupancy is intentionally low —
// DRAM-bound kernels need in-flight bytes, not warps.

#define Z_MIN   (-1.0f)
#define STEP    (2.0f / 24.0f)
#define INVSTEP (12.0f)
#define LMAX    (24.0f)

__device__ __forceinline__ float quant1(float x) {
    float k = rintf((x - Z_MIN) * INVSTEP);
    k = fminf(fmaxf(k, 0.0f), LMAX);
    return fmaf(k, STEP, Z_MIN);
}

__device__ __forceinline__ float4 quant4(float4 a) {
    float4 r;
    r.x = quant1(a.x); r.y = quant1(a.y); r.z = quant1(a.z); r.w = quant1(a.w);
    return r;
}

#define TILE 16   // float4s per thread (256B)

__global__ void __launch_bounds__(256) quant_kernel_v16t(const float4* __restrict__ in,
                                                         float4* __restrict__ out,
                                                         int n4) {
    int base = blockIdx.x * (blockDim.x * TILE) + threadIdx.x;
    int s = blockDim.x;

    if (base + (TILE - 1) * s < n4) {
        // fast path: all in range (every block except possibly the last)
        float4 v[TILE];
        #pragma unroll
        for (int j = 0; j < TILE; j++) v[j] = __ldcg(&in[base + j * s]);
        #pragma unroll
        for (int j = 0; j < TILE; j++) v[j] = quant4(v[j]);
        #pragma unroll
        for (int j = 0; j < TILE; j++) __stcs(&out[base + j * s], v[j]);
    } else {
        #pragma unroll
        for (int j = 0; j < TILE; j++) {
            int i = base + j * s;
            if (i < n4) __stcs(&out[i], quant4(__ldcg(&in[i])));
        }
    }
}

__global__ void __launch_bounds__(256) quant_kernel_tail(const float* __restrict__ in,
                                                         float* __restrict__ out,
                                                         int start, int n) {
    int i = start + blockIdx.x * blockDim.x + threadIdx.x;
    if (i < n) out[i] = quant1(in[i]);
}

extern "C" void kernel_launch(void* const* d_in, const int* in_sizes, int n_in,
                              void* d_out, int out_size) {
    const float* x = (const float*)d_in[0];
    float* out = (float*)d_out;
    int n = in_sizes[0];

    int n4 = n / 4;
    int tail_start = n4 * 4;

    if (n4 > 0) {
        const int threads = 256;
        const int per_block = threads * TILE;        // float4s per block
        int blocks = (n4 + per_block - 1) / per_block;
        quant_kernel_v16t<<<blocks, threads>>>((const float4*)x, (float4*)out, n4);
    }
    if (tail_start < n) {
        int rem = n - tail_start;
        int threads = 256;
        int blocks = (rem + threads - 1) / threads;
        quant_kernel_tail<<<blocks, threads>>>(x, out, tail_start, n);
    }
}

// round 8
// speedup vs baseline: 1.5000x; 1.5000x over previous
#include <cuda_runtime.h>

// Soft quantizer forward == hard nearest-level quantization (straight-through).
// levels[k] = -1 + k*(2/24), k = 0..24.
//
// HBM-streaming kernel at the DRAM roofline (~7.1 TB/s effective achieved).
// Winning structure: block-tiled float4, TILE=8 per thread (128B),
// __ldcg loads (L2-cached, L1-bypass) + __stcs (evict-first) streaming
// stores. This round: 128-thread blocks to recover occupancy (~62% vs 48%)
// at identical per-thread memory shape, plus finer wave-tail granularity.

#define Z_MIN   (-1.0f)
#define STEP    (2.0f / 24.0f)
#define INVSTEP (12.0f)
#define LMAX    (24.0f)

__device__ __forceinline__ float quant1(float x) {
    float k = rintf((x - Z_MIN) * INVSTEP);
    k = fminf(fmaxf(k, 0.0f), LMAX);
    return fmaf(k, STEP, Z_MIN);
}

__device__ __forceinline__ float4 quant4(float4 a) {
    float4 r;
    r.x = quant1(a.x); r.y = quant1(a.y); r.z = quant1(a.z); r.w = quant1(a.w);
    return r;
}

#define TILE 8      // float4s per thread (128B)
#define NTHR 128    // threads per block

__global__ void __launch_bounds__(NTHR) quant_kernel_v8t(const float4* __restrict__ in,
                                                         float4* __restrict__ out,
                                                         int n4) {
    int base = blockIdx.x * (NTHR * TILE) + threadIdx.x;
    const int s = NTHR;

    if (base + (TILE - 1) * s < n4) {
        // fast path: all in range (every block except possibly the last)
        float4 v[TILE];
        #pragma unroll
        for (int j = 0; j < TILE; j++) v[j] = __ldcg(&in[base + j * s]);   // front-batched MLP=8
        #pragma unroll
        for (int j = 0; j < TILE; j++) v[j] = quant4(v[j]);
        #pragma unroll
        for (int j = 0; j < TILE; j++) __stcs(&out[base + j * s], v[j]);
    } else {
        #pragma unroll
        for (int j = 0; j < TILE; j++) {
            int i = base + j * s;
            if (i < n4) __stcs(&out[i], quant4(__ldcg(&in[i])));
        }
    }
}

__global__ void __launch_bounds__(256) quant_kernel_tail(const float* __restrict__ in,
                                                         float* __restrict__ out,
                                                         int start, int n) {
    int i = start + blockIdx.x * blockDim.x + threadIdx.x;
    if (i < n) out[i] = quant1(in[i]);
}

extern "C" void kernel_launch(void* const* d_in, const int* in_sizes, int n_in,
                              void* d_out, int out_size) {
    const float* x = (const float*)d_in[0];
    float* out = (float*)d_out;
    int n = in_sizes[0];

    int n4 = n / 4;
    int tail_start = n4 * 4;

    if (n4 > 0) {
        const int per_block = NTHR * TILE;           // float4s per block
        int blocks = (n4 + per_block - 1) / per_block;
        quant_kernel_v8t<<<blocks, NTHR>>>((const float4*)x, (float4*)out, n4);
    }
    if (tail_start < n) {
        int rem = n - tail_start;
        int threads = 256;
        int blocks = (rem + threads - 1) / threads;
        quant_kernel_tail<<<blocks, threads>>>(x, out, tail_start, n);
    }
}

// round 9
// speedup vs baseline: 1.6650x; 1.1100x over previous
#include <cuda_runtime.h>

// Soft quantizer forward == hard nearest-level quantization (straight-through).
// levels[k] = -1 + k*(2/24), k = 0..24.
//
// HBM-streaming kernel at the DRAM roofline (~7.3 TB/s effective).
// Best-known memory shape (R5): per tile, 8 front-batched __ldcg float4
// loads (L2-cached, L1-bypass) + 8 __stcs (evict-first) stores, 256 threads.
// This round: persistent grid (148 SMs x 5 resident CTAs = 740 CTAs) with a
// grid-stride tile loop — one full resident wave, no wave-transition tail,
// no per-tile CTA relaunch cost.

#define Z_MIN   (-1.0f)
#define STEP    (2.0f / 24.0f)
#define INVSTEP (12.0f)
#define LMAX    (24.0f)

__device__ __forceinline__ float quant1(float x) {
    float k = rintf((x - Z_MIN) * INVSTEP);
    k = fminf(fmaxf(k, 0.0f), LMAX);
    return fmaf(k, STEP, Z_MIN);
}

__device__ __forceinline__ float4 quant4(float4 a) {
    float4 r;
    r.x = quant1(a.x); r.y = quant1(a.y); r.z = quant1(a.z); r.w = quant1(a.w);
    return r;
}

#define TILE 8              // float4s per thread per tile (128B)
#define NTHR 256            // threads per block
#define TILE_F4 (NTHR * TILE)   // float4s per tile = 2048

__global__ void __launch_bounds__(NTHR) quant_kernel_pers(const float4* __restrict__ in,
                                                          float4* __restrict__ out,
                                                          int n4, int ntiles) {
    for (int t = blockIdx.x; t < ntiles; t += gridDim.x) {
        int base = t * TILE_F4 + threadIdx.x;

        if (base + (TILE - 1) * NTHR < n4) {
            // fast path: full tile in range (all tiles except possibly the last)
            float4 v[TILE];
            #pragma unroll
            for (int j = 0; j < TILE; j++) v[j] = __ldcg(&in[base + j * NTHR]);
            #pragma unroll
            for (int j = 0; j < TILE; j++) v[j] = quant4(v[j]);
            #pragma unroll
            for (int j = 0; j < TILE; j++) __stcs(&out[base + j * NTHR], v[j]);
        } else {
            #pragma unroll
            for (int j = 0; j < TILE; j++) {
                int i = base + j * NTHR;
                if (i < n4) __stcs(&out[i], quant4(__ldcg(&in[i])));
            }
        }
    }
}

__global__ void __launch_bounds__(256) quant_kernel_tail(const float* __restrict__ in,
                                                         float* __restrict__ out,
                                                         int start, int n) {
    int i = start + blockIdx.x * blockDim.x + threadIdx.x;
    if (i < n) out[i] = quant1(in[i]);
}

extern "C" void kernel_launch(void* const* d_in, const int* in_sizes, int n_in,
                              void* d_out, int out_size) {
    const float* x = (const float*)d_in[0];
    float* out = (float*)d_out;
    int n = in_sizes[0];

    int n4 = n / 4;
    int tail_start = n4 * 4;

    if (n4 > 0) {
        int ntiles = (n4 + TILE_F4 - 1) / TILE_F4;
        int blocks = 148 * 5;                        // one full resident wave
        if (blocks > ntiles) blocks = ntiles;
        quant_kernel_pers<<<blocks, NTHR>>>((const float4*)x, (float4*)out, n4, ntiles);
    }
    if (tail_start < n) {
        int rem = n - tail_start;
        int threads = 256;
        int blocks = (rem + threads - 1) / threads;
        quant_kernel_tail<<<blocks, threads>>>(x, out, tail_start, n);
    }
}